// round 14
// baseline (speedup 1.0000x reference)
#include <cuda_runtime.h>
#include <cuda_bf16.h>
#include <mma.h>
#include <math.h>
#include <stdint.h>

using namespace nvcuda;

#define NN 50000
#define EE 800000
#define DH 128
#define DOUT 40
#define WLD 136   // padded leading dim for bf16 tiles

// ---------------- scratch (device globals; no allocation allowed) ----------------
__device__ float g_bufA[NN * DH];
__device__ float g_bufB[NN * DH];
__device__ float g_bufC[NN * DH];
__device__ float g_sum[DH];
__device__ float g_sqsum[DH];
__device__ int   g_deg[NN];
__device__ int   g_off[NN + 1];
__device__ int   g_rank[EE];
__device__ int   g_slot[EE];
__device__ __nv_bfloat16 g_Wbf[5][2][128 * WLD];

// ---------------- CSR build ----------------
__global__ void hist_kernel(const int* __restrict__ ei) {
    int e = blockIdx.x * blockDim.x + threadIdx.x;
    if (e >= EE) return;
    int dst = min(max(__ldg(&ei[EE + e]), 0), NN - 1);
    g_rank[e] = atomicAdd(&g_deg[dst], 1);
}

__global__ void __launch_bounds__(1024) scan_kernel() {
    const int CH = (NN + 1023) / 1024;   // 49
    int t = threadIdx.x;
    int base = t * CH;
    int s = 0;
    for (int i = 0; i < CH; i++) {
        int idx = base + i;
        if (idx < NN) s += g_deg[idx];
    }
    __shared__ int sh[1024];
    sh[t] = s;
    __syncthreads();
    for (int off = 1; off < 1024; off <<= 1) {
        int v = (t >= off) ? sh[t - off] : 0;
        __syncthreads();
        sh[t] += v;
        __syncthreads();
    }
    int run = sh[t] - s;   // exclusive
    for (int i = 0; i < CH; i++) {
        int idx = base + i;
        if (idx < NN) {
            g_off[idx] = run;
            run += g_deg[idx];
        }
    }
    if (t == 1023) g_off[NN] = run;
}

// atomic-free fill: pos = off[dst] + rank[e]
__global__ void fill_kernel(const int* __restrict__ ei) {
    int e = blockIdx.x * blockDim.x + threadIdx.x;
    if (e >= EE) return;
    int src = min(max(__ldg(&ei[e]), 0), NN - 1);
    int dst = min(max(__ldg(&ei[EE + e]), 0), NN - 1);
    int pos = __ldg(&g_off[dst]) + g_rank[e];
    g_slot[pos] = src;
}

// ---------------- aggregation: warp per node, agg[i] = x[i] + sum_nbr x[nbr] ----------
// block 0 also zeroes the BN stats accumulators (safe: consuming GEMM runs after us).
__global__ void __launch_bounds__(256) aggregate_kernel(const float* __restrict__ X,
                                                        float* __restrict__ agg) {
    if (blockIdx.x == 0 && threadIdx.x < 128) {
        g_sum[threadIdx.x] = 0.f;
        g_sqsum[threadIdx.x] = 0.f;
    }
    int node = blockIdx.x * 8 + (threadIdx.x >> 5);
    if (node >= NN) return;
    int lane = threadIdx.x & 31;
    const float4* X4 = (const float4*)X;
    float4 a = __ldg(&X4[(size_t)node * 32 + lane]);
    int s = __ldg(&g_off[node]);
    int e = __ldg(&g_off[node + 1]);
    int j = s;
    for (; j + 4 <= e; j += 4) {
        int s0 = __ldg(&g_slot[j + 0]);
        int s1 = __ldg(&g_slot[j + 1]);
        int s2 = __ldg(&g_slot[j + 2]);
        int s3 = __ldg(&g_slot[j + 3]);
        float4 v0 = __ldg(&X4[(size_t)s0 * 32 + lane]);
        float4 v1 = __ldg(&X4[(size_t)s1 * 32 + lane]);
        float4 v2 = __ldg(&X4[(size_t)s2 * 32 + lane]);
        float4 v3 = __ldg(&X4[(size_t)s3 * 32 + lane]);
        a.x += v0.x + v1.x + v2.x + v3.x;
        a.y += v0.y + v1.y + v2.y + v3.y;
        a.z += v0.z + v1.z + v2.z + v3.z;
        a.w += v0.w + v1.w + v2.w + v3.w;
    }
    for (; j < e; j++) {
        int src = __ldg(&g_slot[j]);
        float4 v = __ldg(&X4[(size_t)src * 32 + lane]);
        a.x += v.x; a.y += v.y; a.z += v.z; a.w += v.w;
    }
    ((float4*)agg)[(size_t)node * 32 + lane] = a;
}

// ---------------- W prep ----------------
__global__ void prep_w_kernel(const float* W0, const float* W1, const float* W2,
                              const float* W3, const float* W4) {
    const float* Ws[5] = {W0, W1, W2, W3, W4};
    int p = blockIdx.x >> 3;
    int chunk = blockIdx.x & 7;
    const float* W = Ws[p];
    __nv_bfloat16* hi = g_Wbf[p][0];
    __nv_bfloat16* lo = g_Wbf[p][1];
#pragma unroll
    for (int i = 0; i < 8; i++) {
        int idx = chunk * 2048 + i * 256 + threadIdx.x;
        int k = idx >> 7;
        int n = idx & 127;
        float w = __ldg(&W[idx]);
        __nv_bfloat16 h = __float2bfloat16(w);
        __nv_bfloat16 l = __float2bfloat16(w - __bfloat162float(h));
        hi[k * WLD + n] = h;
        lo[k * WLD + n] = l;
    }
}

// ---------------- cp.async helpers ----------------
__device__ __forceinline__ void cp_async16(void* smem_dst, const void* gmem_src) {
    uint32_t s = (uint32_t)__cvta_generic_to_shared(smem_dst);
    asm volatile("cp.async.cg.shared.global [%0], [%1], 16;" :: "r"(s), "l"(gmem_src));
}
__device__ __forceinline__ void cp_async_commit() {
    asm volatile("cp.async.commit_group;" ::: "memory");
}
__device__ __forceinline__ void cp_async_wait_all() {
    asm volatile("cp.async.wait_group 0;" ::: "memory");
}

// ---------------- tensor-core GEMM (wmma bf16 hi/lo 3-term, fp32 accum) --------------
// 256 threads (8 warps), 64 rows/CTA -> ~106 KB smem -> 2 CTAs/SM for phase overlap.
// Warp w: rows (w&3)*16..+16, cols (w>>2)*64..+64.
// W tiles fetched via cp.async, overlapped with the X convert phase.
// BN_IN: per-column scale/shift from g_sum/g_sqsum + gamma/beta in the prologue.
// STATS: accumulate column sum/sqsum of output into g_sum/g_sqsum.
static const int GSM_TOTAL = 1536 + 2 * (64 * WLD * 2) + 2 * (128 * WLD * 2);  // 105984

template <bool RELU, bool STATS, bool BN_IN>
__global__ void __launch_bounds__(256) gemm_wmma_kernel(
    const float* __restrict__ X,
    const __nv_bfloat16* __restrict__ Whi,
    const __nv_bfloat16* __restrict__ Wlo,
    const float* __restrict__ Bias,
    const float* __restrict__ Gamma,
    const float* __restrict__ Beta,
    float* __restrict__ Y, int nrows)
{
    extern __shared__ char smem[];
    float* sbias  = (float*)smem;
    float* sscale = (float*)(smem + 512);
    float* sshift = (float*)(smem + 1024);
    __nv_bfloat16* Ahi = (__nv_bfloat16*)(smem + 1536);
    __nv_bfloat16* Alo = Ahi + 64 * WLD;
    __nv_bfloat16* Bhi = Alo + 64 * WLD;
    __nv_bfloat16* Blo = Bhi + 128 * WLD;
    float* sout = (float*)(smem + 1536);              // reused after MMA (64x132)
    float* ssum = sout + 64 * 132;                    // [8][128]
    float* ssq  = ssum + 8 * 128;                     // [8][128]

    int tid  = threadIdx.x;
    int row0 = blockIdx.x * 64;

    // W hi/lo tiles -> smem via cp.async (completes during X convert)
    {
        const uint4* sh = (const uint4*)Whi;
        const uint4* sl = (const uint4*)Wlo;
        uint4* dh = (uint4*)Bhi;
        uint4* dl = (uint4*)Blo;
#pragma unroll
        for (int i = 0; i < 9; i++) {
            int j = tid + i * 256;
            if (j < 2176) {
                cp_async16(&dh[j], &sh[j]);
                cp_async16(&dl[j], &sl[j]);
            }
        }
        cp_async_commit();
    }

    if (tid < 128) {
        sbias[tid] = __ldg(&Bias[tid]);
        if (BN_IN) {
            const float invN = 1.0f / (float)NN;
            float mu  = g_sum[tid] * invN;
            float var = g_sqsum[tid] * invN - mu * mu;
            float rs  = rsqrtf(var + 1e-5f);
            float sc  = rs * __ldg(&Gamma[tid]);
            sscale[tid] = sc;
            sshift[tid] = __ldg(&Beta[tid]) - mu * sc;
        }
    }
    if (BN_IN) __syncthreads();   // sscale/sshift ready before convert

    // X tile (64 rows) -> bf16 hi/lo (optional BN+relu on the fly)
    {
        const float4* X4 = (const float4*)X;
        int c4 = tid & 31;
        float4 sc, sh4;
        if (BN_IN) {
            sc  = ((const float4*)sscale)[c4];
            sh4 = ((const float4*)sshift)[c4];
        }
#pragma unroll
        for (int i = 0; i < 8; i++) {
            int idx = tid + i * 256;          // 2048 float4 = 64x128 tile
            int r  = idx >> 5;
            int grow = row0 + r;
            float4 v = make_float4(0.f, 0.f, 0.f, 0.f);
            if (grow < nrows) v = __ldg(&X4[(size_t)grow * 32 + c4]);
            if (BN_IN) {
                v.x = fmaxf(v.x * sc.x + sh4.x, 0.f);
                v.y = fmaxf(v.y * sc.y + sh4.y, 0.f);
                v.z = fmaxf(v.z * sc.z + sh4.z, 0.f);
                v.w = fmaxf(v.w * sc.w + sh4.w, 0.f);
            }
            __nv_bfloat16 h0 = __float2bfloat16(v.x), h1 = __float2bfloat16(v.y),
                          h2 = __float2bfloat16(v.z), h3 = __float2bfloat16(v.w);
            __nv_bfloat16 l0 = __float2bfloat16(v.x - __bfloat162float(h0));
            __nv_bfloat16 l1 = __float2bfloat16(v.y - __bfloat162float(h1));
            __nv_bfloat16 l2 = __float2bfloat16(v.z - __bfloat162float(h2));
            __nv_bfloat16 l3 = __float2bfloat16(v.w - __bfloat162float(h3));
            __nv_bfloat16* ph = Ahi + r * WLD + c4 * 4;
            __nv_bfloat16* pl = Alo + r * WLD + c4 * 4;
            ph[0] = h0; ph[1] = h1; ph[2] = h2; ph[3] = h3;
            pl[0] = l0; pl[1] = l1; pl[2] = l2; pl[3] = l3;
        }
    }
    cp_async_wait_all();   // W tiles landed
    __syncthreads();

    // MMA: warp w -> rows (w&3)*16..+16, cols (w>>2)*64..+64
    int w  = tid >> 5;
    int wr = (w & 3) * 16;
    int wc = (w >> 2) * 64;

    wmma::fragment<wmma::accumulator, 16, 16, 16, float> acc[4];
#pragma unroll
    for (int j = 0; j < 4; j++) wmma::fill_fragment(acc[j], 0.f);

#pragma unroll
    for (int k = 0; k < 8; k++) {
        wmma::fragment<wmma::matrix_a, 16, 16, 16, __nv_bfloat16, wmma::row_major> ah, al;
        wmma::fragment<wmma::matrix_b, 16, 16, 16, __nv_bfloat16, wmma::row_major> bh[4], bl[4];
        wmma::load_matrix_sync(ah, Ahi + wr * WLD + k * 16, WLD);
        wmma::load_matrix_sync(al, Alo + wr * WLD + k * 16, WLD);
#pragma unroll
        for (int j = 0; j < 4; j++) {
            wmma::load_matrix_sync(bh[j], Bhi + (k * 16) * WLD + wc + 16 * j, WLD);
            wmma::load_matrix_sync(bl[j], Blo + (k * 16) * WLD + wc + 16 * j, WLD);
        }
#pragma unroll
        for (int j = 0; j < 4; j++) {
            wmma::mma_sync(acc[j], ah, bh[j], acc[j]);
            wmma::mma_sync(acc[j], ah, bl[j], acc[j]);
            wmma::mma_sync(acc[j], al, bh[j], acc[j]);
        }
    }
    __syncthreads();

#pragma unroll
    for (int j = 0; j < 4; j++)
        wmma::store_matrix_sync(sout + wr * 132 + wc + 16 * j, acc[j], 132,
                                wmma::mem_row_major);
    __syncthreads();

    // bias + relu + global write (+ column stats partials)
    float cs[4] = {0.f, 0.f, 0.f, 0.f};
    float cq[4] = {0.f, 0.f, 0.f, 0.f};
    {
        float4* Y4 = (float4*)Y;
        int c4 = tid & 31;
        float4 b = ((const float4*)sbias)[c4];
#pragma unroll
        for (int i = 0; i < 8; i++) {
            int idx = tid + i * 256;
            int r  = idx >> 5;
            int grow = row0 + r;
            if (grow >= nrows) continue;
            float4 v = ((const float4*)(sout + r * 132))[c4];
            v.x += b.x; v.y += b.y; v.z += b.z; v.w += b.w;
            if (RELU) {
                v.x = fmaxf(v.x, 0.f); v.y = fmaxf(v.y, 0.f);
                v.z = fmaxf(v.z, 0.f); v.w = fmaxf(v.w, 0.f);
            }
            if (STATS) {
                cs[0] += v.x; cq[0] += v.x * v.x;
                cs[1] += v.y; cq[1] += v.y * v.y;
                cs[2] += v.z; cq[2] += v.z * v.z;
                cs[3] += v.w; cq[3] += v.w * v.w;
            }
            Y4[(size_t)grow * 32 + c4] = v;
        }
    }

    if (STATS) {
        __syncthreads();
        int g  = tid >> 5;
        int c4 = tid & 31;
#pragma unroll
        for (int j = 0; j < 4; j++) {
            ssum[g * 128 + c4 * 4 + j] = cs[j];
            ssq[g * 128 + c4 * 4 + j]  = cq[j];
        }
        __syncthreads();
        if (tid < 128) {
            float a = 0.f;
#pragma unroll
            for (int gg = 0; gg < 8; gg++) a += ssum[gg * 128 + tid];
            atomicAdd(&g_sum[tid], a);
        } else {
            int c = tid - 128;
            float a = 0.f;
#pragma unroll
            for (int gg = 0; gg < 8; gg++) a += ssq[gg * 128 + c];
            atomicAdd(&g_sqsum[c], a);
        }
    }
}

// ---------------- fused head: logits = X @ Wl2 + b, then log-softmax ----------------
__global__ void __launch_bounds__(320) gemm40_softmax_kernel(
    const float* __restrict__ X, const float* __restrict__ W,
    const float* __restrict__ B, float* __restrict__ out, int nrows)
{
    __shared__ float slog[128 * 44];

    int t  = threadIdx.x;
    int rg = t / 10;
    int cg = t - rg * 10;
    int row0 = blockIdx.x * 128 + rg * 4;

    const float4* X4 = (const float4*)X;
    const float4* W4 = (const float4*)W;

    int  rowc[4];
    bool val[4];
#pragma unroll
    for (int r = 0; r < 4; r++) {
        int rr = row0 + r;
        val[r]  = rr < nrows;
        rowc[r] = val[r] ? rr : 0;
    }

    float acc[4][4];
#pragma unroll
    for (int r = 0; r < 4; r++)
#pragma unroll
        for (int j = 0; j < 4; j++) acc[r][j] = 0.f;

#pragma unroll 4
    for (int k = 0; k < 128; k += 4) {
        float4 w0 = W4[(k + 0) * 10 + cg];
        float4 w1 = W4[(k + 1) * 10 + cg];
        float4 w2 = W4[(k + 2) * 10 + cg];
        float4 w3 = W4[(k + 3) * 10 + cg];
#pragma unroll
        for (int r = 0; r < 4; r++) {
            float4 xv = X4[rowc[r] * 32 + (k >> 2)];
            acc[r][0] += xv.x * w0.x; acc[r][0] += xv.y * w1.x;
            acc[r][0] += xv.z * w2.x; acc[r][0] += xv.w * w3.x;
            acc[r][1] += xv.x * w0.y; acc[r][1] += xv.y * w1.y;
            acc[r][1] += xv.z * w2.y; acc[r][1] += xv.w * w3.y;
            acc[r][2] += xv.x * w0.z; acc[r][2] += xv.y * w1.z;
            acc[r][2] += xv.z * w2.z; acc[r][2] += xv.w * w3.z;
            acc[r][3] += xv.x * w0.w; acc[r][3] += xv.y * w1.w;
            acc[r][3] += xv.z * w2.w; acc[r][3] += xv.w * w3.w;
        }
    }

    float4 b4 = ((const float4*)B)[cg];
#pragma unroll
    for (int r = 0; r < 4; r++) {
        int lr = rg * 4 + r;
        slog[lr * 44 + cg * 4 + 0] = acc[r][0] + b4.x;
        slog[lr * 44 + cg * 4 + 1] = acc[r][1] + b4.y;
        slog[lr * 44 + cg * 4 + 2] = acc[r][2] + b4.z;
        slog[lr * 44 + cg * 4 + 3] = acc[r][3] + b4.w;
    }
    __syncthreads();

    if (t < 128) {
        int grow = blockIdx.x * 128 + t;
        if (grow < nrows) {
            const float* l = slog + t * 44;
            float v[DOUT];
#pragma unroll
            for (int j = 0; j < DOUT; j++) v[j] = l[j];
            float m = v[0];
#pragma unroll
            for (int j = 1; j < DOUT; j++) m = fmaxf(m, v[j]);
            float s = 0.f;
#pragma unroll
            for (int j = 0; j < DOUT; j++) s += expf(v[j] - m);
            float lse = logf(s) + m;
            float4* o4 = (float4*)(out + (size_t)grow * DOUT);
#pragma unroll
            for (int i = 0; i < 10; i++) {
                float4 o;
                o.x = v[i*4+0] - lse; o.y = v[i*4+1] - lse;
                o.z = v[i*4+2] - lse; o.w = v[i*4+3] - lse;
                o4[i] = o;
            }
        }
    }
}

// ---------------- host launch ----------------
extern "C" void kernel_launch(void* const* d_in, const int* in_sizes, int n_in,
                              void* d_out, int out_size) {
    const float* x   = (const float*)d_in[0];
    const int*   ei  = (const int*)d_in[1];   // int32
    const float* W1a = (const float*)d_in[2];
    const float* b1a = (const float*)d_in[3];
    const float* g1  = (const float*)d_in[4];
    const float* be1 = (const float*)d_in[5];
    const float* W2a = (const float*)d_in[6];
    const float* b2a = (const float*)d_in[7];
    const float* W1b = (const float*)d_in[8];
    const float* b1b = (const float*)d_in[9];
    const float* g2  = (const float*)d_in[10];
    const float* be2 = (const float*)d_in[11];
    const float* W2b = (const float*)d_in[12];
    const float* b2b = (const float*)d_in[13];
    const float* Wl1 = (const float*)d_in[14];
    const float* bl1 = (const float*)d_in[15];
    const float* Wl2 = (const float*)d_in[16];
    const float* bl2 = (const float*)d_in[17];
    float* out = (float*)d_out;

    float *pA, *pB, *pC;
    cudaGetSymbolAddress((void**)&pA, g_bufA);
    cudaGetSymbolAddress((void**)&pB, g_bufB);
    cudaGetSymbolAddress((void**)&pC, g_bufC);
    __nv_bfloat16* wt;
    cudaGetSymbolAddress((void**)&wt, g_Wbf);
    int* pDeg;
    cudaGetSymbolAddress((void**)&pDeg, g_deg);

    cudaFuncSetAttribute(gemm_wmma_kernel<false, true,  false>, cudaFuncAttributeMaxDynamicSharedMemorySize, GSM_TOTAL);
    cudaFuncSetAttribute(gemm_wmma_kernel<true,  false, true >, cudaFuncAttributeMaxDynamicSharedMemorySize, GSM_TOTAL);
    cudaFuncSetAttribute(gemm_wmma_kernel<true,  false, false>, cudaFuncAttributeMaxDynamicSharedMemorySize, GSM_TOTAL);

    const int edgeGrid = (EE + 255) / 256;
    const int aggGrid  = (NN + 7) / 8;
    const int tcGrid   = (NN + 63) / 64;        // 782
    const size_t wpage = (size_t)128 * WLD;

    prep_w_kernel<<<40, 256>>>(W1a, W2a, W1b, W2b, Wl1);
    cudaMemsetAsync(pDeg, 0, NN * sizeof(int));
    hist_kernel<<<edgeGrid, 256>>>(ei);
    scan_kernel<<<1, 1024>>>();
    fill_kernel<<<edgeGrid, 256>>>(ei);
#define WHI(p) (wt + (size_t)(p) * 2 * wpage)
#define WLO(p) (wt + (size_t)(p) * 2 * wpage + wpage)

    // ---- conv1 ----
    aggregate_kernel<<<aggGrid, 256>>>(x, pA);
    gemm_wmma_kernel<false, true, false><<<tcGrid, 256, GSM_TOTAL>>>(
        pA, WHI(0), WLO(0), b1a, nullptr, nullptr, pB, NN);
    gemm_wmma_kernel<true, false, true><<<tcGrid, 256, GSM_TOTAL>>>(
        pB, WHI(1), WLO(1), b2a, g1, be1, pC, NN);

    // ---- conv2 ----
    aggregate_kernel<<<aggGrid, 256>>>(pC, pA);
    gemm_wmma_kernel<false, true, false><<<tcGrid, 256, GSM_TOTAL>>>(
        pA, WHI(2), WLO(2), b1b, nullptr, nullptr, pB, NN);
    gemm_wmma_kernel<true, false, true><<<tcGrid, 256, GSM_TOTAL>>>(
        pB, WHI(3), WLO(3), b2b, g2, be2, pC, NN);

    // ---- head ----
    gemm_wmma_kernel<true, false, false><<<tcGrid, 256, GSM_TOTAL>>>(
        pC, WHI(4), WLO(4), bl1, nullptr, nullptr, pA, NN);
    gemm40_softmax_kernel<<<(NN + 127) / 128, 320>>>(pA, Wl2, bl2, out, NN);
}

// round 15
// speedup vs baseline: 1.1527x; 1.1527x over previous
#include <cuda_runtime.h>
#include <cuda_bf16.h>
#include <mma.h>
#include <math.h>
#include <stdint.h>

using namespace nvcuda;

#define NN 50000
#define EE 800000
#define DH 128
#define DOUT 40
#define WLD 136   // padded leading dim for bf16 tiles
#define HLD 72    // padded leading dim for head B tile (64 cols + 8)

// ---------------- scratch (device globals; no allocation allowed) ----------------
__device__ float g_bufA[NN * DH];
__device__ float g_bufB[NN * DH];
__device__ float g_bufC[NN * DH];
__device__ float g_sum[DH];
__device__ float g_sqsum[DH];
__device__ int   g_deg[NN];
__device__ int   g_off[NN + 1];
__device__ int   g_rank[EE];
__device__ int   g_slot[EE];
__device__ __nv_bfloat16 g_Wbf[5][2][128 * WLD];
__device__ __nv_bfloat16 g_Wl2bf[2][128 * HLD];   // head weight, 64 padded cols

// ---------------- CSR build ----------------
__global__ void hist_kernel(const int* __restrict__ ei) {
    int e = blockIdx.x * blockDim.x + threadIdx.x;
    if (e >= EE) return;
    int dst = min(max(__ldg(&ei[EE + e]), 0), NN - 1);
    g_rank[e] = atomicAdd(&g_deg[dst], 1);
}

__global__ void __launch_bounds__(1024) scan_kernel() {
    const int CH = (NN + 1023) / 1024;   // 49
    int t = threadIdx.x;
    int base = t * CH;
    int s = 0;
    for (int i = 0; i < CH; i++) {
        int idx = base + i;
        if (idx < NN) s += g_deg[idx];
    }
    __shared__ int sh[1024];
    sh[t] = s;
    __syncthreads();
    for (int off = 1; off < 1024; off <<= 1) {
        int v = (t >= off) ? sh[t - off] : 0;
        __syncthreads();
        sh[t] += v;
        __syncthreads();
    }
    int run = sh[t] - s;   // exclusive
    for (int i = 0; i < CH; i++) {
        int idx = base + i;
        if (idx < NN) {
            g_off[idx] = run;
            run += g_deg[idx];
        }
    }
    if (t == 1023) g_off[NN] = run;
}

// atomic-free fill: pos = off[dst] + rank[e]
__global__ void fill_kernel(const int* __restrict__ ei) {
    int e = blockIdx.x * blockDim.x + threadIdx.x;
    if (e >= EE) return;
    int src = min(max(__ldg(&ei[e]), 0), NN - 1);
    int dst = min(max(__ldg(&ei[EE + e]), 0), NN - 1);
    int pos = __ldg(&g_off[dst]) + g_rank[e];
    g_slot[pos] = src;
}

// ---------------- aggregation: warp per node, agg[i] = x[i] + sum_nbr x[nbr] ----------
// block 0 also zeroes the BN stats accumulators (safe: consuming GEMM runs after us).
__global__ void __launch_bounds__(256) aggregate_kernel(const float* __restrict__ X,
                                                        float* __restrict__ agg) {
    if (blockIdx.x == 0 && threadIdx.x < 128) {
        g_sum[threadIdx.x] = 0.f;
        g_sqsum[threadIdx.x] = 0.f;
    }
    int node = blockIdx.x * 8 + (threadIdx.x >> 5);
    if (node >= NN) return;
    int lane = threadIdx.x & 31;
    const float4* X4 = (const float4*)X;
    float4 a = __ldg(&X4[(size_t)node * 32 + lane]);
    int s = __ldg(&g_off[node]);
    int e = __ldg(&g_off[node + 1]);
    int j = s;
    for (; j + 4 <= e; j += 4) {
        int s0 = __ldg(&g_slot[j + 0]);
        int s1 = __ldg(&g_slot[j + 1]);
        int s2 = __ldg(&g_slot[j + 2]);
        int s3 = __ldg(&g_slot[j + 3]);
        float4 v0 = __ldg(&X4[(size_t)s0 * 32 + lane]);
        float4 v1 = __ldg(&X4[(size_t)s1 * 32 + lane]);
        float4 v2 = __ldg(&X4[(size_t)s2 * 32 + lane]);
        float4 v3 = __ldg(&X4[(size_t)s3 * 32 + lane]);
        a.x += v0.x + v1.x + v2.x + v3.x;
        a.y += v0.y + v1.y + v2.y + v3.y;
        a.z += v0.z + v1.z + v2.z + v3.z;
        a.w += v0.w + v1.w + v2.w + v3.w;
    }
    for (; j < e; j++) {
        int src = __ldg(&g_slot[j]);
        float4 v = __ldg(&X4[(size_t)src * 32 + lane]);
        a.x += v.x; a.y += v.y; a.z += v.z; a.w += v.w;
    }
    ((float4*)agg)[(size_t)node * 32 + lane] = a;
}

// ---------------- W prep: blocks 0-39 conv weights, 40-47 head weight ----------------
__global__ void prep_w_kernel(const float* W0, const float* W1, const float* W2,
                              const float* W3, const float* W4, const float* W5) {
    if (blockIdx.x >= 40) {
        // head weight Wl2 [128 x 40] -> padded [128 x 64] hi/lo tiles (stride HLD)
        int chunk = blockIdx.x - 40;   // 0..7, each covers 1024 of 8192 entries
#pragma unroll
        for (int i = 0; i < 4; i++) {
            int idx = chunk * 1024 + i * 256 + threadIdx.x;
            int k = idx >> 6;
            int n = idx & 63;
            float w = (n < DOUT) ? __ldg(&W5[k * DOUT + n]) : 0.f;
            __nv_bfloat16 h = __float2bfloat16(w);
            __nv_bfloat16 l = __float2bfloat16(w - __bfloat162float(h));
            g_Wl2bf[0][k * HLD + n] = h;
            g_Wl2bf[1][k * HLD + n] = l;
        }
        return;
    }
    const float* Ws[5] = {W0, W1, W2, W3, W4};
    int p = blockIdx.x >> 3;
    int chunk = blockIdx.x & 7;
    const float* W = Ws[p];
    __nv_bfloat16* hi = g_Wbf[p][0];
    __nv_bfloat16* lo = g_Wbf[p][1];
#pragma unroll
    for (int i = 0; i < 8; i++) {
        int idx = chunk * 2048 + i * 256 + threadIdx.x;
        int k = idx >> 7;
        int n = idx & 127;
        float w = __ldg(&W[idx]);
        __nv_bfloat16 h = __float2bfloat16(w);
        __nv_bfloat16 l = __float2bfloat16(w - __bfloat162float(h));
        hi[k * WLD + n] = h;
        lo[k * WLD + n] = l;
    }
}

// ---------------- cp.async helpers ----------------
__device__ __forceinline__ void cp_async16(void* smem_dst, const void* gmem_src) {
    uint32_t s = (uint32_t)__cvta_generic_to_shared(smem_dst);
    asm volatile("cp.async.cg.shared.global [%0], [%1], 16;" :: "r"(s), "l"(gmem_src));
}
__device__ __forceinline__ void cp_async_commit() {
    asm volatile("cp.async.commit_group;" ::: "memory");
}
__device__ __forceinline__ void cp_async_wait_all() {
    asm volatile("cp.async.wait_group 0;" ::: "memory");
}

// ---------------- tensor-core GEMM (wmma bf16 hi/lo 3-term, fp32 accum) --------------
// 256 threads (8 warps), 128 rows/CTA (R13 geometry, proven).
// W tiles fetched via cp.async, overlapped with the X convert phase.
static const int GSM_TOTAL = 1536 + 4 * 128 * WLD * 2;   // 140800

template <bool RELU, bool STATS, bool BN_IN>
__global__ void __launch_bounds__(256) gemm_wmma_kernel(
    const float* __restrict__ X,
    const __nv_bfloat16* __restrict__ Whi,
    const __nv_bfloat16* __restrict__ Wlo,
    const float* __restrict__ Bias,
    const float* __restrict__ Gamma,
    const float* __restrict__ Beta,
    float* __restrict__ Y, int nrows)
{
    extern __shared__ char smem[];
    float* sbias  = (float*)smem;
    float* sscale = (float*)(smem + 512);
    float* sshift = (float*)(smem + 1024);
    __nv_bfloat16* Ahi = (__nv_bfloat16*)(smem + 1536);
    __nv_bfloat16* Alo = Ahi + 128 * WLD;
    __nv_bfloat16* Bhi = Alo + 128 * WLD;
    __nv_bfloat16* Blo = Bhi + 128 * WLD;
    float* sout = (float*)(smem + 1536);   // reused after MMA (128x132 floats)

    int tid  = threadIdx.x;
    int row0 = blockIdx.x * 128;

    // W hi/lo tiles -> smem via cp.async (completes during X convert)
    {
        const uint4* sh = (const uint4*)Whi;
        const uint4* sl = (const uint4*)Wlo;
        uint4* dh = (uint4*)Bhi;
        uint4* dl = (uint4*)Blo;
#pragma unroll
        for (int i = 0; i < 9; i++) {
            int j = tid + i * 256;
            if (j < 2176) {
                cp_async16(&dh[j], &sh[j]);
                cp_async16(&dl[j], &sl[j]);
            }
        }
        cp_async_commit();
    }

    if (tid < 128) {
        sbias[tid] = __ldg(&Bias[tid]);
        if (BN_IN) {
            const float invN = 1.0f / (float)NN;
            float mu  = g_sum[tid] * invN;
            float var = g_sqsum[tid] * invN - mu * mu;
            float rs  = rsqrtf(var + 1e-5f);
            float sc  = rs * __ldg(&Gamma[tid]);
            sscale[tid] = sc;
            sshift[tid] = __ldg(&Beta[tid]) - mu * sc;
        }
    }
    if (BN_IN) __syncthreads();   // sscale/sshift ready before convert

    // X tile -> bf16 hi/lo (optional BN+relu on the fly)
    {
        const float4* X4 = (const float4*)X;
        int c4 = tid & 31;
        float4 sc, sh4;
        if (BN_IN) {
            sc  = ((const float4*)sscale)[c4];
            sh4 = ((const float4*)sshift)[c4];
        }
#pragma unroll
        for (int i = 0; i < 16; i++) {
            int idx = tid + i * 256;          // 4096 float4 = 128x128 tile
            int r  = idx >> 5;
            int grow = row0 + r;
            float4 v = make_float4(0.f, 0.f, 0.f, 0.f);
            if (grow < nrows) v = __ldg(&X4[(size_t)grow * 32 + c4]);
            if (BN_IN) {
                v.x = fmaxf(v.x * sc.x + sh4.x, 0.f);
                v.y = fmaxf(v.y * sc.y + sh4.y, 0.f);
                v.z = fmaxf(v.z * sc.z + sh4.z, 0.f);
                v.w = fmaxf(v.w * sc.w + sh4.w, 0.f);
            }
            __nv_bfloat16 h0 = __float2bfloat16(v.x), h1 = __float2bfloat16(v.y),
                          h2 = __float2bfloat16(v.z), h3 = __float2bfloat16(v.w);
            __nv_bfloat16 l0 = __float2bfloat16(v.x - __bfloat162float(h0));
            __nv_bfloat16 l1 = __float2bfloat16(v.y - __bfloat162float(h1));
            __nv_bfloat16 l2 = __float2bfloat16(v.z - __bfloat162float(h2));
            __nv_bfloat16 l3 = __float2bfloat16(v.w - __bfloat162float(h3));
            __nv_bfloat16* ph = Ahi + r * WLD + c4 * 4;
            __nv_bfloat16* pl = Alo + r * WLD + c4 * 4;
            ph[0] = h0; ph[1] = h1; ph[2] = h2; ph[3] = h3;
            pl[0] = l0; pl[1] = l1; pl[2] = l2; pl[3] = l3;
        }
    }
    cp_async_wait_all();   // W tiles landed
    __syncthreads();

    // MMA: warp w -> rows (w&3)*32..+32, cols (w>>2)*64..+64
    int w  = tid >> 5;
    int wr = (w & 3) * 32;
    int wc = (w >> 2) * 64;

    wmma::fragment<wmma::accumulator, 16, 16, 16, float> acc[2][4];
#pragma unroll
    for (int i = 0; i < 2; i++)
#pragma unroll
        for (int j = 0; j < 4; j++) wmma::fill_fragment(acc[i][j], 0.f);

#pragma unroll
    for (int k = 0; k < 8; k++) {
        wmma::fragment<wmma::matrix_a, 16, 16, 16, __nv_bfloat16, wmma::row_major> ah[2], al[2];
        wmma::fragment<wmma::matrix_b, 16, 16, 16, __nv_bfloat16, wmma::row_major> bh[4], bl[4];
#pragma unroll
        for (int i = 0; i < 2; i++) {
            wmma::load_matrix_sync(ah[i], Ahi + (wr + 16 * i) * WLD + k * 16, WLD);
            wmma::load_matrix_sync(al[i], Alo + (wr + 16 * i) * WLD + k * 16, WLD);
        }
#pragma unroll
        for (int j = 0; j < 4; j++) {
            wmma::load_matrix_sync(bh[j], Bhi + (k * 16) * WLD + wc + 16 * j, WLD);
            wmma::load_matrix_sync(bl[j], Blo + (k * 16) * WLD + wc + 16 * j, WLD);
        }
#pragma unroll
        for (int i = 0; i < 2; i++)
#pragma unroll
            for (int j = 0; j < 4; j++) {
                wmma::mma_sync(acc[i][j], ah[i], bh[j], acc[i][j]);
                wmma::mma_sync(acc[i][j], ah[i], bl[j], acc[i][j]);
                wmma::mma_sync(acc[i][j], al[i], bh[j], acc[i][j]);
            }
    }
    __syncthreads();

#pragma unroll
    for (int i = 0; i < 2; i++)
#pragma unroll
        for (int j = 0; j < 4; j++)
            wmma::store_matrix_sync(sout + (wr + 16 * i) * 132 + wc + 16 * j,
                                    acc[i][j], 132, wmma::mem_row_major);
    __syncthreads();

    // bias + relu + global write (+ column stats partials)
    float cs[4] = {0.f, 0.f, 0.f, 0.f};
    float cq[4] = {0.f, 0.f, 0.f, 0.f};
    {
        float4* Y4 = (float4*)Y;
        int c4 = tid & 31;
        float4 b = ((const float4*)sbias)[c4];
#pragma unroll
        for (int i = 0; i < 16; i++) {
            int idx = tid + i * 256;
            int r  = idx >> 5;
            int grow = row0 + r;
            if (grow >= nrows) continue;
            float4 v = ((const float4*)(sout + r * 132))[c4];
            v.x += b.x; v.y += b.y; v.z += b.z; v.w += b.w;
            if (RELU) {
                v.x = fmaxf(v.x, 0.f); v.y = fmaxf(v.y, 0.f);
                v.z = fmaxf(v.z, 0.f); v.w = fmaxf(v.w, 0.f);
            }
            if (STATS) {
                cs[0] += v.x; cq[0] += v.x * v.x;
                cs[1] += v.y; cq[1] += v.y * v.y;
                cs[2] += v.z; cq[2] += v.z * v.z;
                cs[3] += v.w; cq[3] += v.w * v.w;
            }
            Y4[(size_t)grow * 32 + c4] = v;
        }
    }

    if (STATS) {
        __syncthreads();
        float* ssum = sout;           // [8][128]
        float* ssq  = sout + 1024;    // [8][128]
        int g  = tid >> 5;
        int c4 = tid & 31;
#pragma unroll
        for (int j = 0; j < 4; j++) {
            ssum[g * 128 + c4 * 4 + j] = cs[j];
            ssq[g * 128 + c4 * 4 + j]  = cq[j];
        }
        __syncthreads();
        if (tid < 128) {
            float a = 0.f;
#pragma unroll
            for (int gg = 0; gg < 8; gg++) a += ssum[gg * 128 + tid];
            atomicAdd(&g_sum[tid], a);
        } else {
            int c = tid - 128;
            float a = 0.f;
#pragma unroll
            for (int gg = 0; gg < 8; gg++) a += ssq[gg * 128 + c];
            atomicAdd(&g_sqsum[c], a);
        }
    }
}

// ---------------- tensor-core head: logits = X @ Wl2 + b, fused log-softmax ----------
// 256 threads (8 warps), 128 rows/CTA. Warp w: rows w*16..+16, cols 0..64 (40 real).
static const int HSM_TOTAL = 256 + 2 * (128 * WLD * 2) + 2 * (128 * HLD * 2);  // 106496+256

__global__ void __launch_bounds__(256) head_wmma_kernel(
    const float* __restrict__ X,
    const float* __restrict__ Bias,
    float* __restrict__ out, int nrows)
{
    extern __shared__ char smem[];
    float* sbias = (float*)smem;                       // 64 floats
    __nv_bfloat16* Ahi = (__nv_bfloat16*)(smem + 256);
    __nv_bfloat16* Alo = Ahi + 128 * WLD;
    __nv_bfloat16* Bhi = Alo + 128 * WLD;
    __nv_bfloat16* Blo = Bhi + 128 * HLD;
    float* sout = (float*)(smem + 256);                // reused after MMA (128 x HLD)

    int tid  = threadIdx.x;
    int row0 = blockIdx.x * 128;

    // B tiles via cp.async: 128*72 bf16 = 1152 uint4 each
    {
        const uint4* sh = (const uint4*)&g_Wl2bf[0][0];
        const uint4* sl = (const uint4*)&g_Wl2bf[1][0];
        uint4* dh = (uint4*)Bhi;
        uint4* dl = (uint4*)Blo;
#pragma unroll
        for (int i = 0; i < 5; i++) {
            int j = tid + i * 256;
            if (j < 1152) {
                cp_async16(&dh[j], &sh[j]);
                cp_async16(&dl[j], &sl[j]);
            }
        }
        cp_async_commit();
    }
    if (tid < 64) sbias[tid] = (tid < DOUT) ? __ldg(&Bias[tid]) : 0.f;

    // X tile -> bf16 hi/lo
    {
        const float4* X4 = (const float4*)X;
        int c4 = tid & 31;
#pragma unroll
        for (int i = 0; i < 16; i++) {
            int idx = tid + i * 256;
            int r  = idx >> 5;
            int grow = row0 + r;
            float4 v = make_float4(0.f, 0.f, 0.f, 0.f);
            if (grow < nrows) v = __ldg(&X4[(size_t)grow * 32 + c4]);
            __nv_bfloat16 h0 = __float2bfloat16(v.x), h1 = __float2bfloat16(v.y),
                          h2 = __float2bfloat16(v.z), h3 = __float2bfloat16(v.w);
            __nv_bfloat16 l0 = __float2bfloat16(v.x - __bfloat162float(h0));
            __nv_bfloat16 l1 = __float2bfloat16(v.y - __bfloat162float(h1));
            __nv_bfloat16 l2 = __float2bfloat16(v.z - __bfloat162float(h2));
            __nv_bfloat16 l3 = __float2bfloat16(v.w - __bfloat162float(h3));
            __nv_bfloat16* ph = Ahi + r * WLD + c4 * 4;
            __nv_bfloat16* pl = Alo + r * WLD + c4 * 4;
            ph[0] = h0; ph[1] = h1; ph[2] = h2; ph[3] = h3;
            pl[0] = l0; pl[1] = l1; pl[2] = l2; pl[3] = l3;
        }
    }
    cp_async_wait_all();
    __syncthreads();

    int w  = tid >> 5;
    int wr = w * 16;

    wmma::fragment<wmma::accumulator, 16, 16, 16, float> acc[4];
#pragma unroll
    for (int j = 0; j < 4; j++) wmma::fill_fragment(acc[j], 0.f);

#pragma unroll
    for (int k = 0; k < 8; k++) {
        wmma::fragment<wmma::matrix_a, 16, 16, 16, __nv_bfloat16, wmma::row_major> ah, al;
        wmma::fragment<wmma::matrix_b, 16, 16, 16, __nv_bfloat16, wmma::row_major> bh[4], bl[4];
        wmma::load_matrix_sync(ah, Ahi + wr * WLD + k * 16, WLD);
        wmma::load_matrix_sync(al, Alo + wr * WLD + k * 16, WLD);
#pragma unroll
        for (int j = 0; j < 4; j++) {
            wmma::load_matrix_sync(bh[j], Bhi + (k * 16) * HLD + 16 * j, HLD);
            wmma::load_matrix_sync(bl[j], Blo + (k * 16) * HLD + 16 * j, HLD);
        }
#pragma unroll
        for (int j = 0; j < 4; j++) {
            wmma::mma_sync(acc[j], ah, bh[j], acc[j]);
            wmma::mma_sync(acc[j], ah, bl[j], acc[j]);
            wmma::mma_sync(acc[j], al, bh[j], acc[j]);
        }
    }
    __syncthreads();   // done reading tiles before smem reuse

#pragma unroll
    for (int j = 0; j < 4; j++)
        wmma::store_matrix_sync(sout + wr * HLD + 16 * j, acc[j], HLD,
                                wmma::mem_row_major);
    __syncthreads();

    // fused log-softmax: one thread per row (t < 128)
    if (tid < 128) {
        int grow = row0 + tid;
        if (grow < nrows) {
            const float* l = sout + tid * HLD;
            float v[DOUT];
#pragma unroll
            for (int j = 0; j < DOUT; j++) v[j] = l[j] + sbias[j];
            float m = v[0];
#pragma unroll
            for (int j = 1; j < DOUT; j++) m = fmaxf(m, v[j]);
            float s = 0.f;
#pragma unroll
            for (int j = 0; j < DOUT; j++) s += expf(v[j] - m);
            float lse = logf(s) + m;
            float4* o4 = (float4*)(out + (size_t)grow * DOUT);
#pragma unroll
            for (int i = 0; i < 10; i++) {
                float4 o;
                o.x = v[i*4+0] - lse; o.y = v[i*4+1] - lse;
                o.z = v[i*4+2] - lse; o.w = v[i*4+3] - lse;
                o4[i] = o;
            }
        }
    }
}

// ---------------- host launch ----------------
extern "C" void kernel_launch(void* const* d_in, const int* in_sizes, int n_in,
                              void* d_out, int out_size) {
    const float* x   = (const float*)d_in[0];
    const int*   ei  = (const int*)d_in[1];   // int32
    const float* W1a = (const float*)d_in[2];
    const float* b1a = (const float*)d_in[3];
    const float* g1  = (const float*)d_in[4];
    const float* be1 = (const float*)d_in[5];
    const float* W2a = (const float*)d_in[6];
    const float* b2a = (const float*)d_in[7];
    const float* W1b = (const float*)d_in[8];
    const float* b1b = (const float*)d_in[9];
    const float* g2  = (const float*)d_in[10];
    const float* be2 = (const float*)d_in[11];
    const float* W2b = (const float*)d_in[12];
    const float* b2b = (const float*)d_in[13];
    const float* Wl1 = (const float*)d_in[14];
    const float* bl1 = (const float*)d_in[15];
    const float* Wl2 = (const float*)d_in[16];
    const float* bl2 = (const float*)d_in[17];
    float* out = (float*)d_out;

    float *pA, *pB, *pC;
    cudaGetSymbolAddress((void**)&pA, g_bufA);
    cudaGetSymbolAddress((void**)&pB, g_bufB);
    cudaGetSymbolAddress((void**)&pC, g_bufC);
    __nv_bfloat16* wt;
    cudaGetSymbolAddress((void**)&wt, g_Wbf);
    int* pDeg;
    cudaGetSymbolAddress((void**)&pDeg, g_deg);

    cudaFuncSetAttribute(gemm_wmma_kernel<false, true,  false>, cudaFuncAttributeMaxDynamicSharedMemorySize, GSM_TOTAL);
    cudaFuncSetAttribute(gemm_wmma_kernel<true,  false, true >, cudaFuncAttributeMaxDynamicSharedMemorySize, GSM_TOTAL);
    cudaFuncSetAttribute(gemm_wmma_kernel<true,  false, false>, cudaFuncAttributeMaxDynamicSharedMemorySize, GSM_TOTAL);
    cudaFuncSetAttribute(head_wmma_kernel, cudaFuncAttributeMaxDynamicSharedMemorySize, HSM_TOTAL);

    const int edgeGrid = (EE + 255) / 256;
    const int aggGrid  = (NN + 7) / 8;
    const int tcGrid   = (NN + 127) / 128;      // 391
    const size_t wpage = (size_t)128 * WLD;

    prep_w_kernel<<<48, 256>>>(W1a, W2a, W1b, W2b, Wl1, Wl2);
    cudaMemsetAsync(pDeg, 0, NN * sizeof(int));
    hist_kernel<<<edgeGrid, 256>>>(ei);
    scan_kernel<<<1, 1024>>>();
    fill_kernel<<<edgeGrid, 256>>>(ei);
#define WHI(p) (wt + (size_t)(p) * 2 * wpage)
#define WLO(p) (wt + (size_t)(p) * 2 * wpage + wpage)

    // ---- conv1 ----
    aggregate_kernel<<<aggGrid, 256>>>(x, pA);
    gemm_wmma_kernel<false, true, false><<<tcGrid, 256, GSM_TOTAL>>>(
        pA, WHI(0), WLO(0), b1a, nullptr, nullptr, pB, NN);
    gemm_wmma_kernel<true, false, true><<<tcGrid, 256, GSM_TOTAL>>>(
        pB, WHI(1), WLO(1), b2a, g1, be1, pC, NN);

    // ---- conv2 ----
    aggregate_kernel<<<aggGrid, 256>>>(pC, pA);
    gemm_wmma_kernel<false, true, false><<<tcGrid, 256, GSM_TOTAL>>>(
        pA, WHI(2), WLO(2), b1b, nullptr, nullptr, pB, NN);
    gemm_wmma_kernel<true, false, true><<<tcGrid, 256, GSM_TOTAL>>>(
        pB, WHI(3), WLO(3), b2b, g2, be2, pC, NN);

    // ---- head ----
    gemm_wmma_kernel<true, false, false><<<tcGrid, 256, GSM_TOTAL>>>(
        pC, WHI(4), WLO(4), bl1, nullptr, nullptr, pA, NN);
    head_wmma_kernel<<<tcGrid, 256, HSM_TOTAL>>>(pA, bl2, out, NN);
}